// round 8
// baseline (speedup 1.0000x reference)
#include <cuda_runtime.h>
#include <cstdint>

// MoeGate: logits via legacy mma.sync tf32 (3xTF32 split) + exact-fp32 fixup.
// R8: split moved to the PRODUCER (Ahi/Alo/Bhi/Blo planes in smem) -- consumer
// is pure LDS+HMMA. R7 profile showed both pipes <40% (issue 33.7%, tensor
// 35.6%): per-warp split overhead (duplicated 2-8x across warps) was the
// limiter, not warp count. Fixup prefetches W/x chunks across the sync.

#define HDIM   2048
#define NEXP   64
#define KTOP   8
#define BM     128
#define KC     32
#define NCHUNK (HDIM / KC)
#define NTHR   512
#define PITCH  36
#define AH_OFF 0
#define AL_OFF (BM * PITCH)                 // 4608
#define BH_OFF (2 * BM * PITCH)             // 9216
#define BL_OFF (BH_OFF + NEXP * PITCH)      // 11520
#define STG_FLOATS (BL_OFF + NEXP * PITCH)  // 13824
#define SMEM_FLOATS (2 * STG_FLOATS)        // 27648 floats = 110592 B
#define LG_PITCH 65
#define NBLK   128
#define FTOK   16
#define FGRID  148

__device__ float g_pi_part[NBLK * NEXP];
__device__ float g_cnt_part[NBLK * NEXP];
__device__ int   g_flag_cnt = 0;
__device__ int   g_flag_idx[16384];

__device__ __forceinline__ void split_tf32(float v, float& hi, float& lo) {
    uint32_t u = __float_as_uint(v);
    uint32_t h = (u + 0x1000u) & 0xFFFFE000u;
    hi = __uint_as_float(h);
    lo = v - hi;
}
__device__ __forceinline__ void split4(float4 v, float4& hi, float4& lo) {
    split_tf32(v.x, hi.x, lo.x);
    split_tf32(v.y, hi.y, lo.y);
    split_tf32(v.z, hi.z, lo.z);
    split_tf32(v.w, hi.w, lo.w);
}
__device__ __forceinline__ void mma_tf32(float* c, const uint32_t* a, const uint32_t* b) {
    asm volatile(
        "mma.sync.aligned.m16n8k8.row.col.f32.tf32.tf32.f32 "
        "{%0,%1,%2,%3}, {%4,%5,%6,%7}, {%8,%9}, {%0,%1,%2,%3};"
        : "+f"(c[0]), "+f"(c[1]), "+f"(c[2]), "+f"(c[3])
        : "r"(a[0]), "r"(a[1]), "r"(a[2]), "r"(a[3]), "r"(b[0]), "r"(b[1]));
}

__global__ __launch_bounds__(NTHR, 1) void gate_kernel(
    const float* __restrict__ x, const float* __restrict__ w,
    float* __restrict__ out, int T, int S)
{
    extern __shared__ float smem[];
    __shared__ float cnt_s[NEXP];

    const int tid  = threadIdx.x;
    const int wid  = tid >> 5;
    const int lane = tid & 31;
    const int grp  = lane >> 2;
    const int qid  = lane & 3;
    const int t0   = blockIdx.x * BM;
    const int mrow0 = (wid & 7) * 16;     // 8 warps in M
    const int ncol0 = (wid >> 3) * 32;    // 2 warps in N

    if (tid < NEXP) cnt_s[tid] = 0.f;

    float acc[4][4];
#pragma unroll
    for (int j = 0; j < 4; j++)
#pragma unroll
        for (int k = 0; k < 4; k++) acc[j][k] = 0.f;

    const float* xbase = x + (size_t)t0 * HDIM;

    float4 rx[2], rw;
    auto ldg_chunk = [&](int c) {
#pragma unroll
        for (int i = 0; i < 2; i++) {
            int id = tid + NTHR * i;      // 0..1023: 128 rows x 8 segs
            rx[i] = *(const float4*)(xbase + (size_t)(id >> 3) * HDIM + c * KC + (id & 7) * 4);
        }
        rw = *(const float4*)(w + (size_t)(tid >> 3) * HDIM + c * KC + (tid & 7) * 4);
    };
    auto sts_chunk = [&](int st) {        // split once here; consumer is LDS+HMMA only
        float* stg = smem + st * STG_FLOATS;
#pragma unroll
        for (int i = 0; i < 2; i++) {
            int id = tid + NTHR * i;
            int off = (id >> 3) * PITCH + (id & 7) * 4;
            float4 hi, lo;
            split4(rx[i], hi, lo);
            *(float4*)(stg + AH_OFF + off) = hi;
            *(float4*)(stg + AL_OFF + off) = lo;
        }
        {
            int off = (tid >> 3) * PITCH + (tid & 7) * 4;
            float4 hi, lo;
            split4(rw, hi, lo);
            *(float4*)(stg + BH_OFF + off) = hi;
            *(float4*)(stg + BL_OFF + off) = lo;
        }
    };

    ldg_chunk(0);

    for (int c = 0; c < NCHUNK; c++) {
        const int st = c & 1;
        sts_chunk(st);
        __syncthreads();
        if (c + 1 < NCHUNK) ldg_chunk(c + 1);

        const float* stg = smem + st * STG_FLOATS;
        const uint32_t* Ah = (const uint32_t*)(stg + AH_OFF);
        const uint32_t* Al = (const uint32_t*)(stg + AL_OFF);
        const uint32_t* Bh = (const uint32_t*)(stg + BH_OFF);
        const uint32_t* Bl = (const uint32_t*)(stg + BL_OFF);

#pragma unroll
        for (int q = 0; q < KC / 8; q++) {
            const int k0 = q * 8;
            uint32_t ah[4], al[4];
#pragma unroll
            for (int j = 0; j < 4; j++) {
                int off = (mrow0 + grp + ((j & 1) << 3)) * PITCH + k0 + qid + ((j >> 1) << 2);
                ah[j] = Ah[off];
                al[j] = Al[off];
            }
            uint32_t bh[4][2], bl[4][2];
#pragma unroll
            for (int nt = 0; nt < 4; nt++) {
                int off = (ncol0 + nt * 8 + grp) * PITCH + k0 + qid;
                bh[nt][0] = Bh[off];     bh[nt][1] = Bh[off + 4];
                bl[nt][0] = Bl[off];     bl[nt][1] = Bl[off + 4];
            }
#pragma unroll
            for (int nt = 0; nt < 4; nt++) mma_tf32(acc[nt], ah, bh[nt]);
#pragma unroll
            for (int nt = 0; nt < 4; nt++) mma_tf32(acc[nt], ah, bl[nt]);
#pragma unroll
            for (int nt = 0; nt < 4; nt++) mma_tf32(acc[nt], al, bh[nt]);
        }
        __syncthreads();
    }

    // ---- logits -> smem ----
    float* lg = smem;
#pragma unroll
    for (int nt = 0; nt < 4; nt++) {
        int row = mrow0 + grp;
        int col = ncol0 + nt * 8 + 2 * qid;
        lg[row * LG_PITCH + col]           = acc[nt][0];
        lg[row * LG_PITCH + col + 1]       = acc[nt][1];
        lg[(row + 8) * LG_PITCH + col]     = acc[nt][2];
        lg[(row + 8) * LG_PITCH + col + 1] = acc[nt][3];
    }
    __syncthreads();

    // ---- per-token epilogue (threads 0..127) ----
    if (tid < BM) {
        float sc[NEXP];
        float mx = -1e30f;
#pragma unroll
        for (int e = 0; e < NEXP; e++) { sc[e] = lg[tid * LG_PITCH + e]; mx = fmaxf(mx, sc[e]); }
        float sum = 0.f;
#pragma unroll
        for (int e = 0; e < NEXP; e++) { sc[e] = __expf(sc[e] - mx); sum += sc[e]; }
        float inv = 1.f / sum;
#pragma unroll
        for (int e = 0; e < NEXP; e++) sc[e] *= inv;
#pragma unroll
        for (int e = 0; e < NEXP; e++) lg[tid * LG_PITCH + e] = sc[e];

        float vsel[KTOP + 1]; int isel[KTOP + 1]; float wsum = 0.f;
#pragma unroll
        for (int j = 0; j < KTOP + 1; j++) {
            float bv = -1.f; int bi = 0;
#pragma unroll
            for (int e = 0; e < NEXP; e++) if (sc[e] > bv) { bv = sc[e]; bi = e; }
            vsel[j] = bv; isel[j] = bi;
#pragma unroll
            for (int e = 0; e < NEXP; e++) if (e == bi) sc[e] = -1.f;
            if (j < KTOP) { wsum += bv; atomicAdd(&cnt_s[bi], 1.f); }
        }
        bool flag = false;
#pragma unroll
        for (int j = 0; j < KTOP; j++)
            if (vsel[j] - vsel[j + 1] < vsel[j] * 1e-3f + 2e-6f) flag = true;

        size_t t = (size_t)t0 + tid;
        if (flag) {
            int p = atomicAdd(&g_flag_cnt, 1);
            g_flag_idx[p] = (int)t;
        }
        float rn = 1.f / (wsum + 1e-20f);
#pragma unroll
        for (int j = 0; j < KTOP; j++) {
            out[t * KTOP + j] = (float)isel[j];
            out[(size_t)T * KTOP + t * KTOP + j] = vsel[j] * rn;
        }
    }
    __syncthreads();

    if (tid < NEXP) {
        float pe = 0.f;
#pragma unroll 8
        for (int m = 0; m < BM; m++) pe += lg[m * LG_PITCH + tid];
        g_pi_part[blockIdx.x * NEXP + tid]  = pe;
        g_cnt_part[blockIdx.x * NEXP + tid] = cnt_s[tid];
    }
}

// Exact-fp32 fixup: sequential-k fma chain per (token, expert). W/x chunks are
// register-prefetched across the sync to hide L2 latency.
__global__ __launch_bounds__(256) void fixup_kernel(
    const float* __restrict__ x, const float* __restrict__ w,
    float* __restrict__ out, int T)
{
    __shared__ float4 ws4[8 * 66];        // [kq][e], padded row 66
    __shared__ float4 xs4[FTOK * 9];      // [t][kq], padded row 9
    __shared__ float  lgs[FTOK][72];

    const int tid = threadIdx.x;
    const int e   = tid & 63;
    const int tp  = tid >> 6;             // 0..3 -> tokens 4tp..4tp+3
    const int nflag = g_flag_cnt;

    const int wr0 = tid >> 3, wq0 = tid & 7;                 // W load lane (i=0)
    const int wr1 = (tid + 256) >> 3, wq1 = tid & 7;         // W load lane (i=1)
    const int xt = tid >> 3, xq = tid & 7;                   // x load lane (tid<128)

    for (int base = blockIdx.x * FTOK; base < nflag; base += FGRID * FTOK) {
        float acc[4] = {0.f, 0.f, 0.f, 0.f};

        int fi = 0;
        if (tid < 128) {
            fi = (base + xt < nflag) ? g_flag_idx[base + xt] : g_flag_idx[base];
        }
        float4 pw0 = *(const float4*)(w + (size_t)wr0 * HDIM + wq0 * 4);
        float4 pw1 = *(const float4*)(w + (size_t)wr1 * HDIM + wq1 * 4);
        float4 px  = (tid < 128) ? *(const float4*)(x + (size_t)fi * HDIM + xq * 4)
                                 : make_float4(0.f, 0.f, 0.f, 0.f);

        for (int c = 0; c < 64; c++) {
            ws4[wq0 * 66 + wr0] = pw0;
            ws4[wq1 * 66 + wr1] = pw1;
            if (tid < 128) xs4[xt * 9 + xq] = px;
            __syncthreads();

            if (c < 63) {                 // prefetch next chunk while computing
                pw0 = *(const float4*)(w + (size_t)wr0 * HDIM + (c + 1) * 32 + wq0 * 4);
                pw1 = *(const float4*)(w + (size_t)wr1 * HDIM + (c + 1) * 32 + wq1 * 4);
                if (tid < 128)
                    px = *(const float4*)(x + (size_t)fi * HDIM + (c + 1) * 32 + xq * 4);
            }
#pragma unroll
            for (int kq = 0; kq < 8; kq++) {
                float4 wv = ws4[kq * 66 + e];
#pragma unroll
                for (int u = 0; u < 4; u++) {
                    float4 xv = xs4[(4 * tp + u) * 9 + kq];
                    acc[u] = fmaf(xv.x, wv.x, acc[u]);
                    acc[u] = fmaf(xv.y, wv.y, acc[u]);
                    acc[u] = fmaf(xv.z, wv.z, acc[u]);
                    acc[u] = fmaf(xv.w, wv.w, acc[u]);
                }
            }
            __syncthreads();
        }

#pragma unroll
        for (int u = 0; u < 4; u++) lgs[4 * tp + u][e] = acc[u];
        __syncthreads();

        if (tid < FTOK && base + tid < nflag) {
            int t = g_flag_idx[base + tid];
            float sc[NEXP];
            float mx = -1e30f;
#pragma unroll
            for (int j = 0; j < NEXP; j++) { sc[j] = lgs[tid][j]; mx = fmaxf(mx, sc[j]); }
            float sum = 0.f;
#pragma unroll
            for (int j = 0; j < NEXP; j++) { sc[j] = __expf(sc[j] - mx); sum += sc[j]; }
            float inv = 1.f / sum;
#pragma unroll
            for (int j = 0; j < NEXP; j++) sc[j] *= inv;

            float wsel[KTOP]; int isel[KTOP]; float wsum = 0.f;
#pragma unroll
            for (int j = 0; j < KTOP; j++) {
                float bv = -1.f; int bi = 0;
#pragma unroll
                for (int e2 = 0; e2 < NEXP; e2++) if (sc[e2] > bv) { bv = sc[e2]; bi = e2; }
                wsel[j] = bv; isel[j] = bi; wsum += bv;
                sc[bi] = -1.f;
            }
            float rn = 1.f / (wsum + 1e-20f);
#pragma unroll
            for (int j = 0; j < KTOP; j++) {
                out[(size_t)t * KTOP + j] = (float)isel[j];
                out[(size_t)T * KTOP + (size_t)t * KTOP + j] = wsel[j] * rn;
            }
        }
        __syncthreads();
    }
}

__global__ void loss_kernel(float* __restrict__ out, int T, int S, int B) {
    __shared__ float red[256];
    int tid = threadIdx.x;
    if (tid == 0) g_flag_cnt = 0;            // reset for next graph replay
    int b = tid >> 6, e = tid & 63;
    float ps = 0.f, cs = 0.f;
    int blk0 = b * (NBLK / 4);
    for (int blk = blk0; blk < blk0 + NBLK / 4; blk++) {
        ps += g_pi_part[blk * NEXP + e];
        cs += g_cnt_part[blk * NEXP + e];
    }
    float pi = ps / (float)S;
    float fi = cs * ((float)NEXP / (float)(S * KTOP));
    red[tid] = pi * fi;
    __syncthreads();
    for (int s = 128; s > 0; s >>= 1) {
        if (tid < s) red[tid] += red[tid + s];
        __syncthreads();
    }
    if (tid == 0)
        out[(size_t)2 * T * KTOP] = red[0] * 0.01f / (float)B;
}

extern "C" void kernel_launch(void* const* d_in, const int* in_sizes, int n_in,
                              void* d_out, int out_size)
{
    const float* x = (const float*)d_in[0];
    const float* w = (const float*)d_in[1];
    float* out = (float*)d_out;

    int Hrt = in_sizes[1] / NEXP;    // 2048
    int T   = in_sizes[0] / Hrt;     // 16384
    int B   = 4;
    int S   = T / B;                 // 4096

    size_t smem_bytes = SMEM_FLOATS * sizeof(float);   // 110592
    cudaFuncSetAttribute(gate_kernel, cudaFuncAttributeMaxDynamicSharedMemorySize,
                         (int)smem_bytes);

    gate_kernel<<<T / BM, NTHR, smem_bytes>>>(x, w, out, T, S);
    fixup_kernel<<<FGRID, 256>>>(x, w, out, T);
    loss_kernel<<<1, 256>>>(out, T, S, B);
}

// round 9
// speedup vs baseline: 1.2696x; 1.2696x over previous
#include <cuda_runtime.h>
#include <cuda_fp16.h>
#include <cstdint>

// MoeGate: logits via mma.sync m16n8k16 fp16 (3-term fp16 split: hi+lo, drop
// lo*lo -> per-term error ~2^-21, same class as 3xTF32) + exact-fp32 fixup.
// R9: fp16 halves HMMA count, fragment LDS bytes, STS bytes, and smem vs the
// tf32 path (R8 profile: wall 3440cyc/chunk, all pipes <50%, smem+tensor
// co-bound). Fixup FTOK 16->32 to hide prefetch latency and halve sweeps.

#define HDIM   2048
#define NEXP   64
#define KTOP   8
#define BM     128
#define KC     32
#define NCHUNK (HDIM / KC)
#define NTHR   512
#define PH     40                          // smem pitch in halves (conflict-free)
#define AH_OFF 0
#define AL_OFF (BM * PH)                   // 5120 halves
#define BH_OFF (2 * BM * PH)               // 10240
#define BL_OFF (BH_OFF + NEXP * PH)        // 12800
#define STG_HALVES (BL_OFF + NEXP * PH)    // 15360 halves = 30720 B/stage
#define LG_PITCH 65
#define NBLK   128
#define FTOK   32
#define FGRID  148

__device__ float g_pi_part[NBLK * NEXP];
__device__ float g_cnt_part[NBLK * NEXP];
__device__ int   g_flag_cnt = 0;
__device__ int   g_flag_idx[16384];

__device__ __forceinline__ void mma_f16(float* c, const uint32_t* a, const uint32_t* b) {
    asm volatile(
        "mma.sync.aligned.m16n8k16.row.col.f32.f16.f16.f32 "
        "{%0,%1,%2,%3}, {%4,%5,%6,%7}, {%8,%9}, {%0,%1,%2,%3};"
        : "+f"(c[0]), "+f"(c[1]), "+f"(c[2]), "+f"(c[3])
        : "r"(a[0]), "r"(a[1]), "r"(a[2]), "r"(a[3]), "r"(b[0]), "r"(b[1]));
}

// fp16 split: hi = fp16(v), lo = fp16(v - hi). Products hi*hi/hi*lo/lo*hi in
// fp32-accumulating HMMA; dropped lo*lo <= 2^-22|ab|.
__device__ __forceinline__ void split_h2(float a, float b, uint32_t& hi, uint32_t& lo) {
    __half ha = __float2half_rn(a), hb = __float2half_rn(b);
    float ra = a - __half2float(ha), rb = b - __half2float(hb);
    __half2 h = __halves2half2(ha, hb);
    __half2 l = __halves2half2(__float2half_rn(ra), __float2half_rn(rb));
    hi = *(uint32_t*)&h;
    lo = *(uint32_t*)&l;
}

__global__ __launch_bounds__(NTHR, 1) void gate_kernel(
    const float* __restrict__ x, const float* __restrict__ w,
    float* __restrict__ out, int T, int S)
{
    extern __shared__ char smraw[];
    __half* smemh = (__half*)smraw;
    float*  lg    = (float*)smraw;        // logits overlay after GEMM
    __shared__ float cnt_s[NEXP];

    const int tid  = threadIdx.x;
    const int wid  = tid >> 5;
    const int lane = tid & 31;
    const int grp  = lane >> 2;
    const int qid  = lane & 3;
    const int t0   = blockIdx.x * BM;
    const int mrow0 = (wid & 7) * 16;     // 8 warps in M
    const int ncol0 = (wid >> 3) * 32;    // 2 warps in N

    if (tid < NEXP) cnt_s[tid] = 0.f;

    float acc[4][4];
#pragma unroll
    for (int j = 0; j < 4; j++)
#pragma unroll
        for (int k = 0; k < 4; k++) acc[j][k] = 0.f;

    const float* xbase = x + (size_t)t0 * HDIM;

    float4 rx[2], rw;
    auto ldg_chunk = [&](int c) {
#pragma unroll
        for (int i = 0; i < 2; i++) {
            int id = tid + NTHR * i;      // 0..1023: 128 rows x 8 segs
            rx[i] = *(const float4*)(xbase + (size_t)(id >> 3) * HDIM + c * KC + (id & 7) * 4);
        }
        rw = *(const float4*)(w + (size_t)(tid >> 3) * HDIM + c * KC + (tid & 7) * 4);
    };
    auto sts_chunk = [&](int st) {
        __half* stg = smemh + st * STG_HALVES;
#pragma unroll
        for (int i = 0; i < 2; i++) {
            int id = tid + NTHR * i;
            int idx = (id >> 3) * PH + (id & 7) * 4;       // half index, 8B aligned
            uint32_t h0, l0, h1, l1;
            split_h2(rx[i].x, rx[i].y, h0, l0);
            split_h2(rx[i].z, rx[i].w, h1, l1);
            *(uint2*)(stg + AH_OFF + idx) = make_uint2(h0, h1);
            *(uint2*)(stg + AL_OFF + idx) = make_uint2(l0, l1);
        }
        {
            int idx = (tid >> 3) * PH + (tid & 7) * 4;
            uint32_t h0, l0, h1, l1;
            split_h2(rw.x, rw.y, h0, l0);
            split_h2(rw.z, rw.w, h1, l1);
            *(uint2*)(stg + BH_OFF + idx) = make_uint2(h0, h1);
            *(uint2*)(stg + BL_OFF + idx) = make_uint2(l0, l1);
        }
    };

    ldg_chunk(0);

    for (int c = 0; c < NCHUNK; c++) {
        const int st = c & 1;
        sts_chunk(st);
        __syncthreads();
        if (c + 1 < NCHUNK) ldg_chunk(c + 1);

        const __half* stg = smemh + st * STG_HALVES;
        const uint32_t* Ah = (const uint32_t*)(stg + AH_OFF);
        const uint32_t* Al = (const uint32_t*)(stg + AL_OFF);
        const uint32_t* Bh = (const uint32_t*)(stg + BH_OFF);
        const uint32_t* Bl = (const uint32_t*)(stg + BL_OFF);

        // q in {0,1}: k-slice of 16. Fragment indices in half2 (uint32) units,
        // uint32 pitch = PH/2 = 20.
#pragma unroll
        for (int q = 0; q < 2; q++) {
            const int kb = 8 * q + qid;
            uint32_t ah[4], al[4];
            {
                int r0 = (mrow0 + grp) * 20, r1 = (mrow0 + grp + 8) * 20;
                ah[0] = Ah[r0 + kb];     ah[1] = Ah[r1 + kb];
                ah[2] = Ah[r0 + kb + 4]; ah[3] = Ah[r1 + kb + 4];
                al[0] = Al[r0 + kb];     al[1] = Al[r1 + kb];
                al[2] = Al[r0 + kb + 4]; al[3] = Al[r1 + kb + 4];
            }
            uint32_t bh[4][2], bl[4][2];
#pragma unroll
            for (int nt = 0; nt < 4; nt++) {
                int nr = (ncol0 + nt * 8 + grp) * 20;
                bh[nt][0] = Bh[nr + kb]; bh[nt][1] = Bh[nr + kb + 4];
                bl[nt][0] = Bl[nr + kb]; bl[nt][1] = Bl[nr + kb + 4];
            }
#pragma unroll
            for (int nt = 0; nt < 4; nt++) mma_f16(acc[nt], ah, bh[nt]);
#pragma unroll
            for (int nt = 0; nt < 4; nt++) mma_f16(acc[nt], ah, bl[nt]);
#pragma unroll
            for (int nt = 0; nt < 4; nt++) mma_f16(acc[nt], al, bh[nt]);
        }
        __syncthreads();
    }

    // ---- logits -> smem (D m16n8 fragment: c0=(grp,2qid) c1=+1 c2=(grp+8,2qid) c3) ----
#pragma unroll
    for (int nt = 0; nt < 4; nt++) {
        int row = mrow0 + grp;
        int col = ncol0 + nt * 8 + 2 * qid;
        lg[row * LG_PITCH + col]           = acc[nt][0];
        lg[row * LG_PITCH + col + 1]       = acc[nt][1];
        lg[(row + 8) * LG_PITCH + col]     = acc[nt][2];
        lg[(row + 8) * LG_PITCH + col + 1] = acc[nt][3];
    }
    __syncthreads();

    // ---- per-token epilogue (threads 0..127) ----
    if (tid < BM) {
        float sc[NEXP];
        float mx = -1e30f;
#pragma unroll
        for (int e = 0; e < NEXP; e++) { sc[e] = lg[tid * LG_PITCH + e]; mx = fmaxf(mx, sc[e]); }
        float sum = 0.f;
#pragma unroll
        for (int e = 0; e < NEXP; e++) { sc[e] = __expf(sc[e] - mx); sum += sc[e]; }
        float inv = 1.f / sum;
#pragma unroll
        for (int e = 0; e < NEXP; e++) sc[e] *= inv;
#pragma unroll
        for (int e = 0; e < NEXP; e++) lg[tid * LG_PITCH + e] = sc[e];

        float vsel[KTOP + 1]; int isel[KTOP + 1]; float wsum = 0.f;
#pragma unroll
        for (int j = 0; j < KTOP + 1; j++) {
            float bv = -1.f; int bi = 0;
#pragma unroll
            for (int e = 0; e < NEXP; e++) if (sc[e] > bv) { bv = sc[e]; bi = e; }
            vsel[j] = bv; isel[j] = bi;
#pragma unroll
            for (int e = 0; e < NEXP; e++) if (e == bi) sc[e] = -1.f;
            if (j < KTOP) { wsum += bv; atomicAdd(&cnt_s[bi], 1.f); }
        }
        bool flag = false;
#pragma unroll
        for (int j = 0; j < KTOP; j++)
            if (vsel[j] - vsel[j + 1] < vsel[j] * 1e-3f + 2e-6f) flag = true;

        size_t t = (size_t)t0 + tid;
        if (flag) {
            int p = atomicAdd(&g_flag_cnt, 1);
            g_flag_idx[p] = (int)t;
        }
        float rn = 1.f / (wsum + 1e-20f);
#pragma unroll
        for (int j = 0; j < KTOP; j++) {
            out[t * KTOP + j] = (float)isel[j];
            out[(size_t)T * KTOP + t * KTOP + j] = vsel[j] * rn;
        }
    }
    __syncthreads();

    if (tid < NEXP) {
        float pe = 0.f;
#pragma unroll 8
        for (int m = 0; m < BM; m++) pe += lg[m * LG_PITCH + tid];
        g_pi_part[blockIdx.x * NEXP + tid]  = pe;
        g_cnt_part[blockIdx.x * NEXP + tid] = cnt_s[tid];
    }
}

// Exact-fp32 fixup: sequential-k fma chain per (token, expert) -- identical
// arithmetic order to round-1's kernel (0 flips vs reference). 32 tokens per
// CTA iteration so per-chunk compute (~512cyc) hides the prefetch latency.
__global__ __launch_bounds__(256) void fixup_kernel(
    const float* __restrict__ x, const float* __restrict__ w,
    float* __restrict__ out, int T)
{
    __shared__ float4 ws4[8 * 66];        // [kq][e]
    __shared__ float4 xs4[FTOK * 9];      // [t][kq]
    __shared__ float  lgs[FTOK][72];

    const int tid = threadIdx.x;
    const int e   = tid & 63;
    const int tp  = tid >> 6;             // 0..3 -> tokens 8tp..8tp+7
    const int nflag = g_flag_cnt;

    const int wr0 = tid >> 3,        wq = tid & 7;
    const int wr1 = (tid + 256) >> 3;
    const int xt  = tid >> 3,        xq = tid & 7;   // 32 tokens x 8 segs = 256

    for (int base = blockIdx.x * FTOK; base < nflag; base += FGRID * FTOK) {
        float acc[8];
#pragma unroll
        for (int u = 0; u < 8; u++) acc[u] = 0.f;

        int fi = (base + xt < nflag) ? g_flag_idx[base + xt] : g_flag_idx[base];

        float4 pw0 = *(const float4*)(w + (size_t)wr0 * HDIM + wq * 4);
        float4 pw1 = *(const float4*)(w + (size_t)wr1 * HDIM + wq * 4);
        float4 px  = *(const float4*)(x + (size_t)fi * HDIM + xq * 4);

        for (int c = 0; c < 64; c++) {
            ws4[wq * 66 + wr0] = pw0;
            ws4[wq * 66 + wr1] = pw1;
            xs4[xt * 9 + xq]   = px;
            __syncthreads();

            if (c < 63) {
                pw0 = *(const float4*)(w + (size_t)wr0 * HDIM + (c + 1) * 32 + wq * 4);
                pw1 = *(const float4*)(w + (size_t)wr1 * HDIM + (c + 1) * 32 + wq * 4);
                px  = *(const float4*)(x + (size_t)fi * HDIM + (c + 1) * 32 + xq * 4);
            }
#pragma unroll
            for (int kq = 0; kq < 8; kq++) {
                float4 wv = ws4[kq * 66 + e];
#pragma unroll
                for (int u = 0; u < 8; u++) {
                    float4 xv = xs4[(8 * tp + u) * 9 + kq];
                    acc[u] = fmaf(xv.x, wv.x, acc[u]);
                    acc[u] = fmaf(xv.y, wv.y, acc[u]);
                    acc[u] = fmaf(xv.z, wv.z, acc[u]);
                    acc[u] = fmaf(xv.w, wv.w, acc[u]);
                }
            }
            __syncthreads();
        }

#pragma unroll
        for (int u = 0; u < 8; u++) lgs[8 * tp + u][e] = acc[u];
        __syncthreads();

        if (tid < FTOK && base + tid < nflag) {
            int t = g_flag_idx[base + tid];
            float sc[NEXP];
            float mx = -1e30f;
#pragma unroll
            for (int j = 0; j < NEXP; j++) { sc[j] = lgs[tid][j]; mx = fmaxf(mx, sc[j]); }
            float sum = 0.f;
#pragma unroll
            for (int j = 0; j < NEXP; j++) { sc[j] = __expf(sc[j] - mx); sum += sc[j]; }
            float inv = 1.f / sum;
#pragma unroll
            for (int j = 0; j < NEXP; j++) sc[j] *= inv;

            float wsel[KTOP]; int isel[KTOP]; float wsum = 0.f;
#pragma unroll
            for (int j = 0; j < KTOP; j++) {
                float bv = -1.f; int bi = 0;
#pragma unroll
                for (int e2 = 0; e2 < NEXP; e2++) if (sc[e2] > bv) { bv = sc[e2]; bi = e2; }
                wsel[j] = bv; isel[j] = bi; wsum += bv;
                sc[bi] = -1.f;
            }
            float rn = 1.f / (wsum + 1e-20f);
#pragma unroll
            for (int j = 0; j < KTOP; j++) {
                out[(size_t)t * KTOP + j] = (float)isel[j];
                out[(size_t)T * KTOP + (size_t)t * KTOP + j] = wsel[j] * rn;
            }
        }
        __syncthreads();
    }
}

__global__ void loss_kernel(float* __restrict__ out, int T, int S, int B) {
    __shared__ float red[256];
    int tid = threadIdx.x;
    if (tid == 0) g_flag_cnt = 0;            // reset for next graph replay
    int b = tid >> 6, e = tid & 63;
    float ps = 0.f, cs = 0.f;
    int blk0 = b * (NBLK / 4);
    for (int blk = blk0; blk < blk0 + NBLK / 4; blk++) {
        ps += g_pi_part[blk * NEXP + e];
        cs += g_cnt_part[blk * NEXP + e];
    }
    float pi = ps / (float)S;
    float fi = cs * ((float)NEXP / (float)(S * KTOP));
    red[tid] = pi * fi;
    __syncthreads();
    for (int s = 128; s > 0; s >>= 1) {
        if (tid < s) red[tid] += red[tid + s];
        __syncthreads();
    }
    if (tid == 0)
        out[(size_t)2 * T * KTOP] = red[0] * 0.01f / (float)B;
}

extern "C" void kernel_launch(void* const* d_in, const int* in_sizes, int n_in,
                              void* d_out, int out_size)
{
    const float* x = (const float*)d_in[0];
    const float* w = (const float*)d_in[1];
    float* out = (float*)d_out;

    int Hrt = in_sizes[1] / NEXP;    // 2048
    int T   = in_sizes[0] / Hrt;     // 16384
    int B   = 4;
    int S   = T / B;                 // 4096

    size_t smem_bytes = 2 * STG_HALVES * sizeof(__half);   // 61440
    cudaFuncSetAttribute(gate_kernel, cudaFuncAttributeMaxDynamicSharedMemorySize,
                         (int)smem_bytes);

    gate_kernel<<<T / BM, NTHR, smem_bytes>>>(x, w, out, T, S);
    fixup_kernel<<<FGRID, 256>>>(x, w, out, T);
    loss_kernel<<<1, 256>>>(out, T, S, B);
}